// round 1
// baseline (speedup 1.0000x reference)
#include <cuda_runtime.h>
#include <math.h>

// Problem constants
#define BB 4
#define TT 1024
#define DD 1024
#define HH 16
#define DKK 64
#define MROWS (BB*TT)   // 4096

// Scratch (static device globals; no allocation allowed)
__device__ float g_Q[BB*HH*TT*DKK];     // [B,H,T,DK] 16MB
__device__ float g_K[BB*HH*TT*DKK];
__device__ float g_V[BB*HH*TT*DKK];
__device__ float g_attn[BB*TT*DD];      // [B,T,D]
__device__ float g_vmean[BB*HH*DKK];
__device__ float g_c[BB];
__device__ float g_scale[BB];           // 1/(8*tau_b)

// ---------------------------------------------------------------------------
// NT SGEMM: C[i,j] = sum_k A[i,k]*W[j,k] + bias[j]
// A: [4096,1024] rowmajor, W: [1024,1024] rowmajor. BM=BN=128, BK=8, 256 thr.
// MODE 0: C rowmajor [4096,1024]. MODE 1: write [B,H,T,DK] layout.
// ---------------------------------------------------------------------------
template<int MODE>
__global__ __launch_bounds__(256)
void sgemm_nt(const float* __restrict__ A, const float* __restrict__ W,
              const float* __restrict__ bias, float* __restrict__ C) {
    const int K = 1024, N = 1024;
    __shared__ float As[8][128];
    __shared__ float Bs[8][128];
    int tid = threadIdx.x;
    int bm = blockIdx.y * 128, bn = blockIdx.x * 128;
    int lrow = tid >> 1;
    int lcol = (tid & 1) * 4;
    const float* Aptr = A + (size_t)(bm + lrow) * K + lcol;
    const float* Wptr = W + (size_t)(bn + lrow) * K + lcol;
    int tyy = tid >> 4, txx = tid & 15;
    int tm = tyy * 8, tn = txx * 8;
    float acc[8][8];
#pragma unroll
    for (int i = 0; i < 8; i++)
#pragma unroll
        for (int j = 0; j < 8; j++) acc[i][j] = 0.f;

    for (int kt = 0; kt < K; kt += 8) {
        float4 av = *(const float4*)(Aptr + kt);
        float4 bv = *(const float4*)(Wptr + kt);
        As[lcol+0][lrow] = av.x; As[lcol+1][lrow] = av.y;
        As[lcol+2][lrow] = av.z; As[lcol+3][lrow] = av.w;
        Bs[lcol+0][lrow] = bv.x; Bs[lcol+1][lrow] = bv.y;
        Bs[lcol+2][lrow] = bv.z; Bs[lcol+3][lrow] = bv.w;
        __syncthreads();
#pragma unroll
        for (int k = 0; k < 8; k++) {
            float a[8], b[8];
            *(float4*)&a[0] = *(const float4*)&As[k][tm];
            *(float4*)&a[4] = *(const float4*)&As[k][tm+4];
            *(float4*)&b[0] = *(const float4*)&Bs[k][tn];
            *(float4*)&b[4] = *(const float4*)&Bs[k][tn+4];
#pragma unroll
            for (int i = 0; i < 8; i++)
#pragma unroll
                for (int j = 0; j < 8; j++)
                    acc[i][j] = fmaf(a[i], b[j], acc[i][j]);
        }
        __syncthreads();
    }

#pragma unroll
    for (int i = 0; i < 8; i++) {
        int row = bm + tm + i;
#pragma unroll
        for (int j = 0; j < 8; j++) {
            int col = bn + tn + j;
            float v = acc[i][j] + bias[col];
            if (MODE == 0) {
                C[(size_t)row * N + col] = v;
            } else {
                int b = row >> 10, t = row & 1023;
                int h = col >> 6,  dk = col & 63;
                C[(((size_t)(b*HH + h))*TT + t)*DKK + dk] = v;
            }
        }
    }
}

// ---------------------------------------------------------------------------
// Gate: c, scale=1/(8*tau), u = 1-c. One block per batch.
// ---------------------------------------------------------------------------
__global__ void gate_kernel(const float* __restrict__ Q,
                            const float* __restrict__ Wg1, const float* __restrict__ bg1,
                            const float* __restrict__ Wg2, const float* __restrict__ bg2,
                            float* __restrict__ c_out, float* __restrict__ scale_out,
                            float* __restrict__ u_out, int write_u) {
    int b = blockIdx.x;
    float s1 = 0.f, s2 = 0.f;
    for (int d = threadIdx.x; d < DD; d += 256) {
        // context[d] = Q[b, h=d>>6, t=0, dk=d&63]
        float q = Q[((size_t)(b*HH + (d >> 6)))*TT*DKK + (d & 63)];
        s1 += q * Wg1[d];
        s2 += q * Wg2[d];
    }
#pragma unroll
    for (int off = 16; off >= 1; off >>= 1) {
        s1 += __shfl_xor_sync(0xffffffffu, s1, off);
        s2 += __shfl_xor_sync(0xffffffffu, s2, off);
    }
    __shared__ float r1[8], r2[8];
    int lane = threadIdx.x & 31, w = threadIdx.x >> 5;
    if (lane == 0) { r1[w] = s1; r2[w] = s2; }
    __syncthreads();
    if (threadIdx.x == 0) {
        float t1 = 0.f, t2 = 0.f;
        for (int i = 0; i < 8; i++) { t1 += r1[i]; t2 += r2[i]; }
        float z1 = t1 + bg1[0], z2 = t2 + bg2[0];
        float q1 = 1.f / (1.f + expf(-z1));
        float q2 = 1.f / (1.f + expf(-z2));
        float c = fminf(fmaxf(q1 * q2, 1e-8f), 1.0f);
        float tau = (c < 0.3f) ? (1.0f / c) : 1.0f;
        c_out[b] = c;
        scale_out[b] = 1.0f / (8.0f * tau);   // 1/(sqrt(64)*tau)
        if (write_u) u_out[b] = 1.0f - c;
    }
}

// ---------------------------------------------------------------------------
// V mean over T for each (b,h,dk). 64 blocks, 256 threads.
// ---------------------------------------------------------------------------
__global__ void vmean_kernel(const float* __restrict__ V, float* __restrict__ vmean) {
    __shared__ float sm[256];
    int bh = blockIdx.x, tid = threadIdx.x;
    int dk = tid & 63, part = tid >> 6;
    size_t base = (size_t)bh * TT * DKK;
    float s = 0.f;
    for (int t = part; t < TT; t += 4) s += V[base + (size_t)t * DKK + dk];
    sm[tid] = s;
    __syncthreads();
    if (part == 0)
        vmean[bh*DKK + dk] = (sm[dk] + sm[64+dk] + sm[128+dk] + sm[192+dk]) * (1.0f/1024.0f);
}

// ---------------------------------------------------------------------------
// Flash attention: block = (b,h, 128-query tile). 256 threads.
// Thread tile: 8 q-rows x 4 k-cols (S) / 8 q-rows x 4 dk-cols (O).
// Row softmax state reduced with width-16 shuffles.
// out = c * softmax(Q'K^T) V + (1-c) * vmean, Q' pre-scaled by 1/(8*tau).
// ---------------------------------------------------------------------------
__global__ __launch_bounds__(256)
void attn_kernel(const float* __restrict__ Qg, const float* __restrict__ Kg,
                 const float* __restrict__ Vg, const float* __restrict__ vmean,
                 const float* __restrict__ c_arr, const float* __restrict__ scale_arr,
                 float* __restrict__ out) {
    extern __shared__ float smx[];
    float* Qs = smx;                 // 128*65
    float* Ps = Qs + 128*65;         // 128*65
    float* Ks = Ps + 128*65;         // 64*65
    float* Vs = Ks + 64*65;          // 64*65

    int tid = threadIdx.x;
    int bh = blockIdx.y;
    int b = bh >> 4, h = bh & 15;
    int q0 = blockIdx.x * 128;
    float scale = scale_arr[b];
    float cg = c_arr[b];
    size_t base = (size_t)bh * TT * DKK;

    // Load Q tile (scaled)
#pragma unroll
    for (int it = 0; it < 8; it++) {
        int e = it * 256 + tid;
        int r = e >> 4, c4 = (e & 15) * 4;
        float4 v = *(const float4*)(Qg + base + (size_t)(q0 + r) * 64 + c4);
        float* dst = Qs + r * 65 + c4;
        dst[0] = v.x * scale; dst[1] = v.y * scale;
        dst[2] = v.z * scale; dst[3] = v.w * scale;
    }

    int tyy = tid >> 4, txx = tid & 15;
    int qr = tyy * 8;     // query row base within tile
    int kc = txx * 4;     // k col (and dk col) base

    float m[8], l[8], O[8][4];
#pragma unroll
    for (int i = 0; i < 8; i++) {
        m[i] = -1e30f; l[i] = 0.f;
#pragma unroll
        for (int j = 0; j < 4; j++) O[i][j] = 0.f;
    }

    for (int kt = 0; kt < 16; kt++) {
        int k0 = kt * 64;
#pragma unroll
        for (int it = 0; it < 4; it++) {
            int e = it * 256 + tid;
            int r = e >> 4, c4 = (e & 15) * 4;
            float4 kv = *(const float4*)(Kg + base + (size_t)(k0 + r) * 64 + c4);
            float4 vv = *(const float4*)(Vg + base + (size_t)(k0 + r) * 64 + c4);
            float* kd = Ks + r * 65 + c4;
            kd[0] = kv.x; kd[1] = kv.y; kd[2] = kv.z; kd[3] = kv.w;
            float* vd = Vs + r * 65 + c4;
            vd[0] = vv.x; vd[1] = vv.y; vd[2] = vv.z; vd[3] = vv.w;
        }
        __syncthreads();   // also covers initial Q load on first iter

        float S[8][4];
#pragma unroll
        for (int i = 0; i < 8; i++)
#pragma unroll
            for (int j = 0; j < 4; j++) S[i][j] = 0.f;

#pragma unroll 4
        for (int d = 0; d < 64; d++) {
            float bb0 = Ks[(kc+0)*65 + d];
            float bb1 = Ks[(kc+1)*65 + d];
            float bb2 = Ks[(kc+2)*65 + d];
            float bb3 = Ks[(kc+3)*65 + d];
#pragma unroll
            for (int i = 0; i < 8; i++) {
                float a = Qs[(qr+i)*65 + d];
                S[i][0] = fmaf(a, bb0, S[i][0]);
                S[i][1] = fmaf(a, bb1, S[i][1]);
                S[i][2] = fmaf(a, bb2, S[i][2]);
                S[i][3] = fmaf(a, bb3, S[i][3]);
            }
        }

        // online softmax update per row (16 lanes own one row-group)
#pragma unroll
        for (int i = 0; i < 8; i++) {
            float mt = fmaxf(fmaxf(S[i][0], S[i][1]), fmaxf(S[i][2], S[i][3]));
            mt = fmaxf(mt, __shfl_xor_sync(0xffffffffu, mt, 8, 16));
            mt = fmaxf(mt, __shfl_xor_sync(0xffffffffu, mt, 4, 16));
            mt = fmaxf(mt, __shfl_xor_sync(0xffffffffu, mt, 2, 16));
            mt = fmaxf(mt, __shfl_xor_sync(0xffffffffu, mt, 1, 16));
            float mn = fmaxf(m[i], mt);
            float f = __expf(m[i] - mn);
            float ls = 0.f;
#pragma unroll
            for (int j = 0; j < 4; j++) {
                float p = __expf(S[i][j] - mn);
                S[i][j] = p;
                ls += p;
            }
            ls += __shfl_xor_sync(0xffffffffu, ls, 8, 16);
            ls += __shfl_xor_sync(0xffffffffu, ls, 4, 16);
            ls += __shfl_xor_sync(0xffffffffu, ls, 2, 16);
            ls += __shfl_xor_sync(0xffffffffu, ls, 1, 16);
            l[i] = l[i] * f + ls;
            m[i] = mn;
#pragma unroll
            for (int j = 0; j < 4; j++) O[i][j] *= f;
            float* pr = Ps + (qr + i) * 65 + kc;
            pr[0] = S[i][0]; pr[1] = S[i][1]; pr[2] = S[i][2]; pr[3] = S[i][3];
        }
        __syncthreads();

        // O += P @ V
#pragma unroll 4
        for (int k = 0; k < 64; k++) {
            float v0 = Vs[k*65 + kc + 0];
            float v1 = Vs[k*65 + kc + 1];
            float v2 = Vs[k*65 + kc + 2];
            float v3 = Vs[k*65 + kc + 3];
#pragma unroll
            for (int i = 0; i < 8; i++) {
                float p = Ps[(qr+i)*65 + k];
                O[i][0] = fmaf(p, v0, O[i][0]);
                O[i][1] = fmaf(p, v1, O[i][1]);
                O[i][2] = fmaf(p, v2, O[i][2]);
                O[i][3] = fmaf(p, v3, O[i][3]);
            }
        }
        __syncthreads();
    }

    float one_minus_c = 1.0f - cg;
#pragma unroll
    for (int i = 0; i < 8; i++) {
        float inv = 1.0f / l[i];
        int q = q0 + qr + i;
#pragma unroll
        for (int j = 0; j < 4; j++) {
            int dk = kc + j;
            out[((size_t)b * TT + q) * DD + h * DKK + dk] =
                cg * O[i][j] * inv + one_minus_c * vmean[bh * DKK + dk];
        }
    }
}

// ---------------------------------------------------------------------------
extern "C" void kernel_launch(void* const* d_in, const int* in_sizes, int n_in,
                              void* d_out, int out_size) {
    const float* x   = (const float*)d_in[0];
    const float* Wq  = (const float*)d_in[1];
    const float* bq  = (const float*)d_in[2];
    const float* Wk  = (const float*)d_in[3];
    const float* bk  = (const float*)d_in[4];
    const float* Wv  = (const float*)d_in[5];
    const float* bv  = (const float*)d_in[6];
    const float* Wo  = (const float*)d_in[7];
    const float* bo  = (const float*)d_in[8];
    const float* Wg1 = (const float*)d_in[9];
    const float* bg1 = (const float*)d_in[10];
    const float* Wg2 = (const float*)d_in[11];
    const float* bg2 = (const float*)d_in[12];
    float* out = (float*)d_out;

    float *pQ, *pK, *pV, *pAttn, *pVm, *pC, *pS;
    cudaGetSymbolAddress((void**)&pQ, g_Q);
    cudaGetSymbolAddress((void**)&pK, g_K);
    cudaGetSymbolAddress((void**)&pV, g_V);
    cudaGetSymbolAddress((void**)&pAttn, g_attn);
    cudaGetSymbolAddress((void**)&pVm, g_vmean);
    cudaGetSymbolAddress((void**)&pC, g_c);
    cudaGetSymbolAddress((void**)&pS, g_scale);

    dim3 gemm_grid(1024/128, MROWS/128);   // (8, 32)
    sgemm_nt<1><<<gemm_grid, 256>>>(x, Wq, bq, pQ);
    sgemm_nt<1><<<gemm_grid, 256>>>(x, Wk, bk, pK);
    sgemm_nt<1><<<gemm_grid, 256>>>(x, Wv, bv, pV);

    int write_u = (out_size >= BB*TT*DD + BB) ? 1 : 0;
    gate_kernel<<<BB, 256>>>(pQ, Wg1, bg1, Wg2, bg2, pC, pS,
                             out + (size_t)BB*TT*DD, write_u);
    vmean_kernel<<<BB*HH, 256>>>(pV, pVm);

    const int attn_smem = (128*65 + 128*65 + 64*65 + 64*65) * 4; // 99840 B
    cudaFuncSetAttribute(attn_kernel, cudaFuncAttributeMaxDynamicSharedMemorySize, attn_smem);
    dim3 attn_grid(TT/128, BB*HH);          // (8, 64)
    attn_kernel<<<attn_grid, 256, attn_smem>>>(pQ, pK, pV, pVm, pC, pS, pAttn);

    sgemm_nt<0><<<gemm_grid, 256>>>(pAttn, Wo, bo, out);
}